// round 1
// baseline (speedup 1.0000x reference)
#include <cuda_runtime.h>
#include <cstdint>

#define BATCH 1024
#define SEQ   256
#define CDIM  512
#define HEAD  64
#define MROWS (BATCH * SEQ)

// Scratch for projected Q, K, V (device globals: allocation-free contract).
__device__ float g_Q[(size_t)MROWS * HEAD];
__device__ float g_K[(size_t)MROWS * HEAD];
__device__ float g_V[(size_t)MROWS * HEAD];

__device__ __forceinline__ uint32_t f2tf32(float x) {
    uint32_t r;
    asm("cvt.rna.tf32.f32 %0, %1;" : "=r"(r) : "f"(x));
    return r;
}

__device__ __forceinline__ void mma_tf32(float d[4], const uint32_t a[4], const uint32_t b[2]) {
    asm volatile(
        "mma.sync.aligned.m16n8k8.row.col.f32.tf32.tf32.f32 "
        "{%0,%1,%2,%3}, {%4,%5,%6,%7}, {%8,%9}, {%0,%1,%2,%3};"
        : "+f"(d[0]), "+f"(d[1]), "+f"(d[2]), "+f"(d[3])
        : "r"(a[0]), "r"(a[1]), "r"(a[2]), "r"(a[3]), "r"(b[0]), "r"(b[1]));
}

// ============================================================================
// Kernel 1: QKV projection. [MROWS, 512] x [512, 192] with 3xTF32 split
// (A = x hi/lo, B = W hi/lo; D += Ah*Bh + Ah*Bl + Al*Bh) for fp32-level accuracy.
// Block tile 128(M) x 192(N), K-chunk 16. 8 warps = 4(M) x 2(N); warp tile 32x96.
// ============================================================================
#define K1_BM 128
#define K1_BK 16

__global__ void __launch_bounds__(256, 1)
qkv_proj_kernel(const float* __restrict__ x, const float* __restrict__ Wq,
                const float* __restrict__ Wk, const float* __restrict__ Wv) {
    __shared__ uint32_t As_hi[K1_BM][20];   // stride 20: (20*gid+tig)%32 distinct
    __shared__ uint32_t As_lo[K1_BM][20];
    __shared__ uint32_t Bs_hi[K1_BK][200];  // stride 200: (8*tig+gid)%32 distinct
    __shared__ uint32_t Bs_lo[K1_BK][200];

    const int tid    = threadIdx.x;
    const int lane   = tid & 31;
    const int wid    = tid >> 5;
    const int warp_m = wid & 3;   // 0..3
    const int warp_n = wid >> 2;  // 0..1
    const int gid    = lane >> 2; // 0..7
    const int tig    = lane & 3;  // 0..3

    const int row0 = blockIdx.x * K1_BM;

    float acc[2][12][4];
#pragma unroll
    for (int mt = 0; mt < 2; mt++)
#pragma unroll
        for (int nt = 0; nt < 12; nt++)
#pragma unroll
            for (int i = 0; i < 4; i++) acc[mt][nt][i] = 0.f;

    for (int kc = 0; kc < CDIM; kc += K1_BK) {
        __syncthreads();
        // ---- load A tile: 128 x 16 fp32, split into tf32 hi/lo ----
#pragma unroll
        for (int s = 0; s < 2; s++) {
            int idx4 = s * 256 + tid;       // 0..511 float4 slots
            int r = idx4 >> 2;              // 4 float4 per row of 16
            int c = (idx4 & 3) * 4;
            float4 v = *reinterpret_cast<const float4*>(
                &x[(size_t)(row0 + r) * CDIM + kc + c]);
            float f[4] = {v.x, v.y, v.z, v.w};
            uint32_t h[4], l[4];
#pragma unroll
            for (int i = 0; i < 4; i++) {
                h[i] = f2tf32(f[i]);
                l[i] = f2tf32(f[i] - __uint_as_float(h[i]));
            }
            *reinterpret_cast<uint4*>(&As_hi[r][c]) = make_uint4(h[0], h[1], h[2], h[3]);
            *reinterpret_cast<uint4*>(&As_lo[r][c]) = make_uint4(l[0], l[1], l[2], l[3]);
        }
        // ---- load B tile: 16 x 192 (Wq|Wk|Wv), split into tf32 hi/lo ----
#pragma unroll
        for (int s = 0; s < 3; s++) {
            int idx4 = s * 256 + tid;       // 0..767
            int k  = idx4 / 48;             // 48 float4 per k-row (192 floats)
            int n0 = (idx4 % 48) * 4;
            const float* wp = (n0 < 64) ? Wq : ((n0 < 128) ? Wk : Wv);
            float4 v = *reinterpret_cast<const float4*>(&wp[(kc + k) * HEAD + (n0 & 63)]);
            float f[4] = {v.x, v.y, v.z, v.w};
            uint32_t h[4], l[4];
#pragma unroll
            for (int i = 0; i < 4; i++) {
                h[i] = f2tf32(f[i]);
                l[i] = f2tf32(f[i] - __uint_as_float(h[i]));
            }
            *reinterpret_cast<uint4*>(&Bs_hi[k][n0]) = make_uint4(h[0], h[1], h[2], h[3]);
            *reinterpret_cast<uint4*>(&Bs_lo[k][n0]) = make_uint4(l[0], l[1], l[2], l[3]);
        }
        __syncthreads();

#pragma unroll
        for (int kk = 0; kk < 2; kk++) {
            const int kb = kk * 8;
            uint32_t ah[2][4], al[2][4];
#pragma unroll
            for (int mt = 0; mt < 2; mt++) {
                int r = warp_m * 32 + mt * 16 + gid;
                ah[mt][0] = As_hi[r][kb + tig];
                ah[mt][1] = As_hi[r + 8][kb + tig];
                ah[mt][2] = As_hi[r][kb + tig + 4];
                ah[mt][3] = As_hi[r + 8][kb + tig + 4];
                al[mt][0] = As_lo[r][kb + tig];
                al[mt][1] = As_lo[r + 8][kb + tig];
                al[mt][2] = As_lo[r][kb + tig + 4];
                al[mt][3] = As_lo[r + 8][kb + tig + 4];
            }
#pragma unroll
            for (int nt = 0; nt < 12; nt++) {
                int n = warp_n * 96 + nt * 8 + gid;
                uint32_t bh[2], bl[2];
                bh[0] = Bs_hi[kb + tig][n];
                bh[1] = Bs_hi[kb + tig + 4][n];
                bl[0] = Bs_lo[kb + tig][n];
                bl[1] = Bs_lo[kb + tig + 4][n];
#pragma unroll
                for (int mt = 0; mt < 2; mt++) {
                    mma_tf32(acc[mt][nt], ah[mt], bh);
                    mma_tf32(acc[mt][nt], ah[mt], bl);
                    mma_tf32(acc[mt][nt], al[mt], bh);
                }
            }
        }
    }

    // ---- writeback to Q/K/V scratch ----
#pragma unroll
    for (int mt = 0; mt < 2; mt++) {
        int r = row0 + warp_m * 32 + mt * 16 + gid;
#pragma unroll
        for (int nt = 0; nt < 12; nt++) {
            int n = warp_n * 96 + nt * 8 + tig * 2;
            float* dst = (n < 64) ? g_Q : ((n < 128) ? g_K : g_V);
            int h = n & 63;
            *reinterpret_cast<float2*>(&dst[(size_t)r * HEAD + h]) =
                make_float2(acc[mt][nt][0], acc[mt][nt][1]);
            *reinterpret_cast<float2*>(&dst[(size_t)(r + 8) * HEAD + h]) =
                make_float2(acc[mt][nt][2], acc[mt][nt][3]);
        }
    }
}

// ============================================================================
// Kernel 2: causal flash attention. One block per (batch, 64-row q-tile),
// 4 warps x 16 q-rows. Q frags register-resident (1/8 scale folded before
// tf32 cvt). K tile smem reused for P. Online softmax in fp32. tf32 MMAs.
// ============================================================================
__global__ void __launch_bounds__(128)
attn_kernel(float* __restrict__ out) {
    __shared__ uint32_t KPs[64][68];  // K tile, then reused as P tile
    __shared__ uint32_t Vs[64][72];   // stride 72: (8*tig+gid)%32 distinct for PV B-frags

    const int b   = blockIdx.y;
    const int qt  = blockIdx.x;
    const int tid = threadIdx.x;
    const int lane = tid & 31;
    const int w   = tid >> 5;     // warp 0..3 -> q rows w*16..w*16+15
    const int gid = lane >> 2;
    const int tig = lane & 3;

    // Q fragments: 8 k-steps x 4 regs, pre-scaled by HEAD^-0.5 = 1/8
    uint32_t qf[8][4];
    {
        const size_t qbase = ((size_t)b * SEQ + (size_t)qt * 64 + w * 16) * HEAD;
#pragma unroll
        for (int kk = 0; kk < 8; kk++) {
            int k = kk * 8 + tig;
            qf[kk][0] = f2tf32(g_Q[qbase + gid * HEAD + k] * 0.125f);
            qf[kk][1] = f2tf32(g_Q[qbase + (gid + 8) * HEAD + k] * 0.125f);
            qf[kk][2] = f2tf32(g_Q[qbase + gid * HEAD + k + 4] * 0.125f);
            qf[kk][3] = f2tf32(g_Q[qbase + (gid + 8) * HEAD + k + 4] * 0.125f);
        }
    }

    float m0 = -1e30f, m1 = -1e30f, l0 = 0.f, l1 = 0.f;
    float o[8][4];
#pragma unroll
    for (int nt = 0; nt < 8; nt++)
#pragma unroll
        for (int i = 0; i < 4; i++) o[nt][i] = 0.f;

    for (int j = 0; j <= qt; j++) {
        __syncthreads();  // previous iteration's P/V reads done before overwrite
        const size_t kvb = ((size_t)b * SEQ + (size_t)j * 64) * HEAD;
#pragma unroll
        for (int s = 0; s < 8; s++) {
            int idx4 = s * 128 + tid;   // 1024 float4 per tile
            int key = idx4 >> 4;
            int h   = (idx4 & 15) * 4;
            float4 kv = *reinterpret_cast<const float4*>(&g_K[kvb + (size_t)key * HEAD + h]);
            float4 vv = *reinterpret_cast<const float4*>(&g_V[kvb + (size_t)key * HEAD + h]);
            *reinterpret_cast<uint4*>(&KPs[key][h]) =
                make_uint4(f2tf32(kv.x), f2tf32(kv.y), f2tf32(kv.z), f2tf32(kv.w));
            *reinterpret_cast<uint4*>(&Vs[key][h]) =
                make_uint4(f2tf32(vv.x), f2tf32(vv.y), f2tf32(vv.z), f2tf32(vv.w));
        }
        __syncthreads();

        // ---- S = (Q*scale) @ K^T : 16x64 per warp ----
        float sc[8][4];
#pragma unroll
        for (int nt = 0; nt < 8; nt++)
#pragma unroll
            for (int i = 0; i < 4; i++) sc[nt][i] = 0.f;

#pragma unroll
        for (int kk = 0; kk < 8; kk++) {
            int k = kk * 8 + tig;
#pragma unroll
            for (int nt = 0; nt < 8; nt++) {
                uint32_t bf[2];
                bf[0] = KPs[nt * 8 + gid][k];
                bf[1] = KPs[nt * 8 + gid][k + 4];
                mma_tf32(sc[nt], qf[kk], bf);
            }
        }

        // ---- causal mask on the diagonal tile ----
        if (j == qt) {
            int q0 = w * 16 + gid, q1 = q0 + 8;
#pragma unroll
            for (int nt = 0; nt < 8; nt++) {
                int kc = nt * 8 + tig * 2;
                if (kc > q0)     sc[nt][0] = -1e30f;
                if (kc + 1 > q0) sc[nt][1] = -1e30f;
                if (kc > q1)     sc[nt][2] = -1e30f;
                if (kc + 1 > q1) sc[nt][3] = -1e30f;
            }
        }

        // ---- online softmax (rows r=gid and r=gid+8, reduce over 4-lane quad) ----
        float rm0 = -1e30f, rm1 = -1e30f;
#pragma unroll
        for (int nt = 0; nt < 8; nt++) {
            rm0 = fmaxf(rm0, fmaxf(sc[nt][0], sc[nt][1]));
            rm1 = fmaxf(rm1, fmaxf(sc[nt][2], sc[nt][3]));
        }
        rm0 = fmaxf(rm0, __shfl_xor_sync(0xffffffffu, rm0, 1));
        rm0 = fmaxf(rm0, __shfl_xor_sync(0xffffffffu, rm0, 2));
        rm1 = fmaxf(rm1, __shfl_xor_sync(0xffffffffu, rm1, 1));
        rm1 = fmaxf(rm1, __shfl_xor_sync(0xffffffffu, rm1, 2));

        float mn0 = fmaxf(m0, rm0), mn1 = fmaxf(m1, rm1);
        float a0 = __expf(m0 - mn0), a1 = __expf(m1 - mn1);

        float rs0 = 0.f, rs1 = 0.f;
#pragma unroll
        for (int nt = 0; nt < 8; nt++) {
            sc[nt][0] = __expf(sc[nt][0] - mn0);
            sc[nt][1] = __expf(sc[nt][1] - mn0);
            sc[nt][2] = __expf(sc[nt][2] - mn1);
            sc[nt][3] = __expf(sc[nt][3] - mn1);
            rs0 += sc[nt][0] + sc[nt][1];
            rs1 += sc[nt][2] + sc[nt][3];
        }
        rs0 += __shfl_xor_sync(0xffffffffu, rs0, 1);
        rs0 += __shfl_xor_sync(0xffffffffu, rs0, 2);
        rs1 += __shfl_xor_sync(0xffffffffu, rs1, 1);
        rs1 += __shfl_xor_sync(0xffffffffu, rs1, 2);

        l0 = l0 * a0 + rs0;
        l1 = l1 * a1 + rs1;
        m0 = mn0; m1 = mn1;

#pragma unroll
        for (int nt = 0; nt < 8; nt++) {
            o[nt][0] *= a0; o[nt][1] *= a0;
            o[nt][2] *= a1; o[nt][3] *= a1;
        }

        __syncthreads();  // all warps done reading K tile before P overwrites it
#pragma unroll
        for (int nt = 0; nt < 8; nt++) {
            int col = nt * 8 + tig * 2;
            KPs[w * 16 + gid][col]         = f2tf32(sc[nt][0]);
            KPs[w * 16 + gid][col + 1]     = f2tf32(sc[nt][1]);
            KPs[w * 16 + gid + 8][col]     = f2tf32(sc[nt][2]);
            KPs[w * 16 + gid + 8][col + 1] = f2tf32(sc[nt][3]);
        }
        __syncwarp();  // P rows are warp-private

        // ---- O += P @ V ----
#pragma unroll
        for (int kk = 0; kk < 8; kk++) {
            int k = kk * 8 + tig;
            uint32_t af[4];
            af[0] = KPs[w * 16 + gid][k];
            af[1] = KPs[w * 16 + gid + 8][k];
            af[2] = KPs[w * 16 + gid][k + 4];
            af[3] = KPs[w * 16 + gid + 8][k + 4];
#pragma unroll
            for (int nt = 0; nt < 8; nt++) {
                uint32_t bf[2];
                bf[0] = Vs[kk * 8 + tig][nt * 8 + gid];
                bf[1] = Vs[kk * 8 + tig + 4][nt * 8 + gid];
                mma_tf32(o[nt], af, bf);
            }
        }
    }

    // ---- normalize and write out ----
    float inv0 = 1.f / l0, inv1 = 1.f / l1;
    const size_t ob = ((size_t)b * SEQ + (size_t)qt * 64 + w * 16) * HEAD;
#pragma unroll
    for (int nt = 0; nt < 8; nt++) {
        int h = nt * 8 + tig * 2;
        *reinterpret_cast<float2*>(&out[ob + gid * HEAD + h]) =
            make_float2(o[nt][0] * inv0, o[nt][1] * inv0);
        *reinterpret_cast<float2*>(&out[ob + (gid + 8) * HEAD + h]) =
            make_float2(o[nt][2] * inv1, o[nt][3] * inv1);
    }
}

extern "C" void kernel_launch(void* const* d_in, const int* in_sizes, int n_in,
                              void* d_out, int out_size) {
    (void)in_sizes; (void)n_in; (void)out_size;
    const float* x  = (const float*)d_in[0];
    const float* Wq = (const float*)d_in[1];
    const float* Wk = (const float*)d_in[2];
    const float* Wv = (const float*)d_in[3];
    float* out = (float*)d_out;

    qkv_proj_kernel<<<MROWS / K1_BM, 256>>>(x, Wq, Wk, Wv);
    attn_kernel<<<dim3(SEQ / 64, BATCH), 128>>>(out);
}

// round 3
// speedup vs baseline: 1.9242x; 1.9242x over previous
#include <cuda_runtime.h>
#include <cuda_fp16.h>
#include <cstdint>

#define BATCH 1024
#define SEQ   256
#define CDIM  512
#define HEAD  64
#define MROWS (BATCH * SEQ)

// Scratch (device globals: allocation-free contract).
__device__ float g_Q[(size_t)MROWS * HEAD];
__device__ float g_K[(size_t)MROWS * HEAD];
__device__ float g_V[(size_t)MROWS * HEAD];
// Pre-split, pre-transposed weights: [N=192][K=512] fp16 hi/lo.
__device__ uint16_t g_Wh[192 * 512];
__device__ uint16_t g_Wl[192 * 512];

// ---------------------------------------------------------------------------
// mma.sync helpers (legacy pipe — tcgen05 is unavailable in this build path)
// ---------------------------------------------------------------------------
__device__ __forceinline__ void mma_f16(float d[4], const uint32_t a[4], const uint32_t b[2]) {
    asm volatile(
        "mma.sync.aligned.m16n8k16.row.col.f32.f16.f16.f32 "
        "{%0,%1,%2,%3}, {%4,%5,%6,%7}, {%8,%9}, {%0,%1,%2,%3};"
        : "+f"(d[0]), "+f"(d[1]), "+f"(d[2]), "+f"(d[3])
        : "r"(a[0]), "r"(a[1]), "r"(a[2]), "r"(a[3]), "r"(b[0]), "r"(b[1]));
}
__device__ __forceinline__ uint32_t f2h2(float a, float b) {
    __half2 h = __floats2half2_rn(a, b);
    return *reinterpret_cast<uint32_t*>(&h);
}

// ---------------------------------------------------------------------------
// Prep: split + transpose W into [192][512] fp16 hi/lo
// ---------------------------------------------------------------------------
__global__ void wsplit_kernel(const float* __restrict__ Wq, const float* __restrict__ Wk,
                              const float* __restrict__ Wv) {
    int i = blockIdx.x * 256 + threadIdx.x;  // 0 .. 192*512-1
    if (i >= 192 * 512) return;
    int n = i >> 9, k = i & 511;
    const float* W = (n < 64) ? Wq : ((n < 128) ? Wk : Wv);
    float v = W[k * HEAD + (n & 63)];
    __half h = __float2half_rn(v);
    __half l = __float2half_rn(v - __half2float(h));
    g_Wh[i] = __half_as_ushort(h);
    g_Wl[i] = __half_as_ushort(l);
}

// ---------------------------------------------------------------------------
// Kernel 1: QKV projection, fp16-split m16n8k16, double-buffered.
// Block tile 128(M) x 192(N), BK=32 (2 x k16). 8 warps = 4M x 2N, warp 32x96.
// smem per stage (word stride 20 = conflict-free): Ah,Al 128x20w; Bh,Bl 192x20w.
// ---------------------------------------------------------------------------
#define STAGE_B   51200
#define AH_OFF    0
#define AL_OFF    10240
#define BH_OFF    20480
#define BL_OFF    35840
#define QKV_SMEM  (2 * STAGE_B)   // 102400

__global__ void __launch_bounds__(256, 1)
qkv_proj_kernel(const float* __restrict__ x) {
    extern __shared__ char smem[];
    const int tid    = threadIdx.x;
    const int lane   = tid & 31;
    const int wid    = tid >> 5;
    const int warp_m = wid & 3;
    const int warp_n = wid >> 2;
    const int gid    = lane >> 2;
    const int tig    = lane & 3;
    const int row0   = blockIdx.x * 128;

    float acc[2][12][4];
#pragma unroll
    for (int mt = 0; mt < 2; mt++)
#pragma unroll
        for (int nt = 0; nt < 12; nt++)
#pragma unroll
            for (int i = 0; i < 4; i++) acc[mt][nt][i] = 0.f;

    // A prefetch registers: 4 float4 per thread per chunk
    float4 av[4];
    const int a_r[4] = {tid >> 3, (256 + tid) >> 3, (512 + tid) >> 3, (768 + tid) >> 3};
    const int a_q = tid & 7;  // same for all 4 since stride 256 = 32 rows

    // ---- prologue: chunk 0 ----
    {
        // B chunk 0 via cp.async
#pragma unroll
        for (int p = 0; p < 2; p++) {
            const uint16_t* W = p ? g_Wl : g_Wh;
            const int dstb = p ? BL_OFF : BH_OFF;
#pragma unroll
            for (int s3 = 0; s3 < 3; s3++) {
                int ui = s3 * 256 + tid;
                int n = ui >> 2, ch = ui & 3;
                uint32_t dst;
                asm("{ .reg .u64 t; cvta.to.shared.u64 t, %1; cvt.u32.u64 %0, t; }"
                    : "=r"(dst) : "l"(smem + dstb + n * 80 + ch * 16));
                asm volatile("cp.async.ca.shared.global [%0], [%1], 16;"
                             :: "r"(dst), "l"(W + n * 512 + ch * 8));
            }
        }
        asm volatile("cp.async.commit_group;" ::: "memory");
        // A chunk 0 LDG
#pragma unroll
        for (int i = 0; i < 4; i++)
            av[i] = *reinterpret_cast<const float4*>(
                &x[(size_t)(row0 + a_r[i]) * CDIM + a_q * 4]);
    }

    for (int c = 0; c < 16; c++) {
        const int cur = (c & 1) * STAGE_B;
        asm volatile("cp.async.wait_group 0;" ::: "memory");

        // ---- convert+store A(c) into stage cur ----
#pragma unroll
        for (int i = 0; i < 4; i++) {
            float4 v = av[i];
            uint32_t h0 = f2h2(v.x, v.y), h1 = f2h2(v.z, v.w);
            __half2 hh0 = *reinterpret_cast<__half2*>(&h0);
            __half2 hh1 = *reinterpret_cast<__half2*>(&h1);
            float2 b0 = __half22float2(hh0), b1 = __half22float2(hh1);
            uint32_t l0 = f2h2(v.x - b0.x, v.y - b0.y);
            uint32_t l1 = f2h2(v.z - b1.x, v.w - b1.y);
            int off = a_r[i] * 80 + a_q * 8;
            *reinterpret_cast<uint2*>(smem + cur + AH_OFF + off) = make_uint2(h0, h1);
            *reinterpret_cast<uint2*>(smem + cur + AL_OFF + off) = make_uint2(l0, l1);
        }
        __syncthreads();

        // ---- issue next chunk's loads (overlap with MMAs) ----
        if (c + 1 < 16) {
            const int nxt = ((c + 1) & 1) * STAGE_B;
            const int kc = (c + 1) * 32;
#pragma unroll
            for (int i = 0; i < 4; i++)
                av[i] = *reinterpret_cast<const float4*>(
                    &x[(size_t)(row0 + a_r[i]) * CDIM + kc + a_q * 4]);
#pragma unroll
            for (int p = 0; p < 2; p++) {
                const uint16_t* W = p ? g_Wl : g_Wh;
                const int dstb = nxt + (p ? BL_OFF : BH_OFF);
#pragma unroll
                for (int s3 = 0; s3 < 3; s3++) {
                    int ui = s3 * 256 + tid;
                    int n = ui >> 2, ch = ui & 3;
                    uint32_t dst;
                    asm("{ .reg .u64 t; cvta.to.shared.u64 t, %1; cvt.u32.u64 %0, t; }"
                        : "=r"(dst) : "l"(smem + dstb + n * 80 + ch * 16));
                    asm volatile("cp.async.ca.shared.global [%0], [%1], 16;"
                                 :: "r"(dst), "l"(W + n * 512 + kc + ch * 8));
                }
            }
            asm volatile("cp.async.commit_group;" ::: "memory");
        }

        // ---- MMAs for chunk c ----
        const uint32_t* Ah = reinterpret_cast<const uint32_t*>(smem + cur + AH_OFF);
        const uint32_t* Al = reinterpret_cast<const uint32_t*>(smem + cur + AL_OFF);
        const uint32_t* Bh = reinterpret_cast<const uint32_t*>(smem + cur + BH_OFF);
        const uint32_t* Bl = reinterpret_cast<const uint32_t*>(smem + cur + BL_OFF);
#pragma unroll
        for (int kk = 0; kk < 2; kk++) {
            const int kw = kk * 8 + tig;
            uint32_t ah[2][4], al[2][4];
#pragma unroll
            for (int mt = 0; mt < 2; mt++) {
                int r = warp_m * 32 + mt * 16 + gid;
                ah[mt][0] = Ah[r * 20 + kw];
                ah[mt][1] = Ah[(r + 8) * 20 + kw];
                ah[mt][2] = Ah[r * 20 + kw + 4];
                ah[mt][3] = Ah[(r + 8) * 20 + kw + 4];
                al[mt][0] = Al[r * 20 + kw];
                al[mt][1] = Al[(r + 8) * 20 + kw];
                al[mt][2] = Al[r * 20 + kw + 4];
                al[mt][3] = Al[(r + 8) * 20 + kw + 4];
            }
#pragma unroll
            for (int nt = 0; nt < 12; nt++) {
                int n = warp_n * 96 + nt * 8 + gid;
                uint32_t bh[2], bl[2];
                bh[0] = Bh[n * 20 + kw];
                bh[1] = Bh[n * 20 + kw + 4];
                bl[0] = Bl[n * 20 + kw];
                bl[1] = Bl[n * 20 + kw + 4];
#pragma unroll
                for (int mt = 0; mt < 2; mt++) {
                    mma_f16(acc[mt][nt], ah[mt], bh);
                    mma_f16(acc[mt][nt], ah[mt], bl);
                    mma_f16(acc[mt][nt], al[mt], bh);
                }
            }
        }
        __syncthreads();
    }

    // ---- writeback ----
#pragma unroll
    for (int mt = 0; mt < 2; mt++) {
        int r = row0 + warp_m * 32 + mt * 16 + gid;
#pragma unroll
        for (int nt = 0; nt < 12; nt++) {
            int n = warp_n * 96 + nt * 8 + tig * 2;
            float* dst = (n < 64) ? g_Q : ((n < 128) ? g_K : g_V);
            int h = n & 63;
            *reinterpret_cast<float2*>(&dst[(size_t)r * HEAD + h]) =
                make_float2(acc[mt][nt][0], acc[mt][nt][1]);
            *reinterpret_cast<float2*>(&dst[(size_t)(r + 8) * HEAD + h]) =
                make_float2(acc[mt][nt][2], acc[mt][nt][3]);
        }
    }
}

// ---------------------------------------------------------------------------
// Kernel 2: causal flash attention (unchanged: tf32 mma.sync, 136.8us)
// ---------------------------------------------------------------------------
__device__ __forceinline__ uint32_t f2tf32(float x) {
    uint32_t r;
    asm("cvt.rna.tf32.f32 %0, %1;" : "=r"(r) : "f"(x));
    return r;
}
__device__ __forceinline__ void mma_tf32(float d[4], const uint32_t a[4], const uint32_t b[2]) {
    asm volatile(
        "mma.sync.aligned.m16n8k8.row.col.f32.tf32.tf32.f32 "
        "{%0,%1,%2,%3}, {%4,%5,%6,%7}, {%8,%9}, {%0,%1,%2,%3};"
        : "+f"(d[0]), "+f"(d[1]), "+f"(d[2]), "+f"(d[3])
        : "r"(a[0]), "r"(a[1]), "r"(a[2]), "r"(a[3]), "r"(b[0]), "r"(b[1]));
}

__global__ void __launch_bounds__(128)
attn_kernel(float* __restrict__ out) {
    __shared__ uint32_t KPs[64][68];
    __shared__ uint32_t Vs[64][72];

    const int b = blockIdx.y;
    const int qt = blockIdx.x;
    const int tid = threadIdx.x;
    const int lane = tid & 31;
    const int w = tid >> 5;
    const int gid = lane >> 2;
    const int tig = lane & 3;

    uint32_t qf[8][4];
    {
        const size_t qbase = ((size_t)b * SEQ + (size_t)qt * 64 + w * 16) * HEAD;
#pragma unroll
        for (int kk = 0; kk < 8; kk++) {
            int k = kk * 8 + tig;
            qf[kk][0] = f2tf32(g_Q[qbase + gid * HEAD + k] * 0.125f);
            qf[kk][1] = f2tf32(g_Q[qbase + (gid + 8) * HEAD + k] * 0.125f);
            qf[kk][2] = f2tf32(g_Q[qbase + gid * HEAD + k + 4] * 0.125f);
            qf[kk][3] = f2tf32(g_Q[qbase + (gid + 8) * HEAD + k + 4] * 0.125f);
        }
    }

    float m0 = -1e30f, m1 = -1e30f, l0 = 0.f, l1 = 0.f;
    float o[8][4];
#pragma unroll
    for (int nt = 0; nt < 8; nt++)
#pragma unroll
        for (int i = 0; i < 4; i++) o[nt][i] = 0.f;

    for (int j = 0; j <= qt; j++) {
        __syncthreads();
        const size_t kvb = ((size_t)b * SEQ + (size_t)j * 64) * HEAD;
#pragma unroll
        for (int s = 0; s < 8; s++) {
            int idx4 = s * 128 + tid;
            int key = idx4 >> 4;
            int h = (idx4 & 15) * 4;
            float4 kv = *reinterpret_cast<const float4*>(&g_K[kvb + (size_t)key * HEAD + h]);
            float4 vv = *reinterpret_cast<const float4*>(&g_V[kvb + (size_t)key * HEAD + h]);
            *reinterpret_cast<uint4*>(&KPs[key][h]) =
                make_uint4(f2tf32(kv.x), f2tf32(kv.y), f2tf32(kv.z), f2tf32(kv.w));
            *reinterpret_cast<uint4*>(&Vs[key][h]) =
                make_uint4(f2tf32(vv.x), f2tf32(vv.y), f2tf32(vv.z), f2tf32(vv.w));
        }
        __syncthreads();

        float sc[8][4];
#pragma unroll
        for (int nt = 0; nt < 8; nt++)
#pragma unroll
            for (int i = 0; i < 4; i++) sc[nt][i] = 0.f;

#pragma unroll
        for (int kk = 0; kk < 8; kk++) {
            int k = kk * 8 + tig;
#pragma unroll
            for (int nt = 0; nt < 8; nt++) {
                uint32_t bf[2];
                bf[0] = KPs[nt * 8 + gid][k];
                bf[1] = KPs[nt * 8 + gid][k + 4];
                mma_tf32(sc[nt], qf[kk], bf);
            }
        }

        if (j == qt) {
            int q0 = w * 16 + gid, q1 = q0 + 8;
#pragma unroll
            for (int nt = 0; nt < 8; nt++) {
                int kc = nt * 8 + tig * 2;
                if (kc > q0) sc[nt][0] = -1e30f;
                if (kc + 1 > q0) sc[nt][1] = -1e30f;
                if (kc > q1) sc[nt][2] = -1e30f;
                if (kc + 1 > q1) sc[nt][3] = -1e30f;
            }
        }

        float rm0 = -1e30f, rm1 = -1e30f;
#pragma unroll
        for (int nt = 0; nt < 8; nt++) {
            rm0 = fmaxf(rm0, fmaxf(sc[nt][0], sc[nt][1]));
            rm1 = fmaxf(rm1, fmaxf(sc[nt][2], sc[nt][3]));
        }
        rm0 = fmaxf(rm0, __shfl_xor_sync(0xffffffffu, rm0, 1));
        rm0 = fmaxf(rm0, __shfl_xor_sync(0xffffffffu, rm0, 2));
        rm1 = fmaxf(rm1, __shfl_xor_sync(0xffffffffu, rm1, 1));
        rm1 = fmaxf(rm1, __shfl_xor_sync(0xffffffffu, rm1, 2));

        float mn0 = fmaxf(m0, rm0), mn1 = fmaxf(m1, rm1);
        float a0 = __expf(m0 - mn0), a1 = __expf(m1 - mn1);

        float rs0 = 0.f, rs1 = 0.f;
#pragma unroll
        for (int nt = 0; nt < 8; nt++) {
            sc[nt][0] = __expf(sc[nt][0] - mn0);
            sc[nt][1] = __expf(sc[nt][1] - mn0);
            sc[nt][2] = __expf(sc[nt][2] - mn1);
            sc[nt][3] = __expf(sc[nt][3] - mn1);
            rs0 += sc[nt][0] + sc[nt][1];
            rs1 += sc[nt][2] + sc[nt][3];
        }
        rs0 += __shfl_xor_sync(0xffffffffu, rs0, 1);
        rs0 += __shfl_xor_sync(0xffffffffu, rs0, 2);
        rs1 += __shfl_xor_sync(0xffffffffu, rs1, 1);
        rs1 += __shfl_xor_sync(0xffffffffu, rs1, 2);

        l0 = l0 * a0 + rs0;
        l1 = l1 * a1 + rs1;
        m0 = mn0; m1 = mn1;

#pragma unroll
        for (int nt = 0; nt < 8; nt++) {
            o[nt][0] *= a0; o[nt][1] *= a0;
            o[nt][2] *= a1; o[nt][3] *= a1;
        }

        __syncthreads();
#pragma unroll
        for (int nt = 0; nt < 8; nt++) {
            int col = nt * 8 + tig * 2;
            KPs[w * 16 + gid][col] = f2tf32(sc[nt][0]);
            KPs[w * 16 + gid][col + 1] = f2tf32(sc[nt][1]);
            KPs[w * 16 + gid + 8][col] = f2tf32(sc[nt][2]);
            KPs[w * 16 + gid + 8][col + 1] = f2tf32(sc[nt][3]);
        }
        __syncwarp();

#pragma unroll
        for (int kk = 0; kk < 8; kk++) {
            int k = kk * 8 + tig;
            uint32_t af[4];
            af[0] = KPs[w * 16 + gid][k];
            af[1] = KPs[w * 16 + gid + 8][k];
            af[2] = KPs[w * 16 + gid][k + 4];
            af[3] = KPs[w * 16 + gid + 8][k + 4];
#pragma unroll
            for (int nt = 0; nt < 8; nt++) {
                uint32_t bf[2];
                bf[0] = Vs[kk * 8 + tig][nt * 8 + gid];
                bf[1] = Vs[kk * 8 + tig + 4][nt * 8 + gid];
                mma_tf32(o[nt], af, bf);
            }
        }
    }

    float inv0 = 1.f / l0, inv1 = 1.f / l1;
    const size_t ob = ((size_t)b * SEQ + (size_t)qt * 64 + w * 16) * HEAD;
#pragma unroll
    for (int nt = 0; nt < 8; nt++) {
        int h = nt * 8 + tig * 2;
        *reinterpret_cast<float2*>(&out[ob + gid * HEAD + h]) =
            make_float2(o[nt][0] * inv0, o[nt][1] * inv0);
        *reinterpret_cast<float2*>(&out[ob + (gid + 8) * HEAD + h]) =
            make_float2(o[nt][2] * inv1, o[nt][3] * inv1);
    }
}

extern "C" void kernel_launch(void* const* d_in, const int* in_sizes, int n_in,
                              void* d_out, int out_size) {
    (void)in_sizes; (void)n_in; (void)out_size;
    const float* x = (const float*)d_in[0];
    const float* Wq = (const float*)d_in[1];
    const float* Wk = (const float*)d_in[2];
    const float* Wv = (const float*)d_in[3];
    float* out = (float*)d_out;

    cudaFuncSetAttribute(qkv_proj_kernel, cudaFuncAttributeMaxDynamicSharedMemorySize,
                         QKV_SMEM);

    wsplit_kernel<<<(192 * 512 + 255) / 256, 256>>>(Wq, Wk, Wv);
    qkv_proj_kernel<<<MROWS / 128, 256, QKV_SMEM>>>(x);
    attn_kernel<<<dim3(SEQ / 64, BATCH), 128>>>(out);
}

// round 4
// speedup vs baseline: 1.9390x; 1.0076x over previous
#include <cuda_runtime.h>
#include <cuda_fp16.h>
#include <cstdint>

#define BATCH 1024
#define SEQ   256
#define CDIM  512
#define HEAD  64
#define MROWS (BATCH * SEQ)

// Scratch: Q (pre-scaled by 0.125), K, V stored as tf32 bit patterns.
__device__ uint32_t g_Q[(size_t)MROWS * HEAD];
__device__ uint32_t g_K[(size_t)MROWS * HEAD];
__device__ uint32_t g_V[(size_t)MROWS * HEAD];
// Pre-split, pre-transposed weights: [N=192][K=512] fp16 hi/lo.
__device__ uint16_t g_Wh[192 * 512];
__device__ uint16_t g_Wl[192 * 512];

// ---------------------------------------------------------------------------
// mma.sync helpers (legacy pipe — tcgen05 unavailable in this build path)
// ---------------------------------------------------------------------------
__device__ __forceinline__ void mma_f16(float d[4], const uint32_t a[4], const uint32_t b[2]) {
    asm volatile(
        "mma.sync.aligned.m16n8k16.row.col.f32.f16.f16.f32 "
        "{%0,%1,%2,%3}, {%4,%5,%6,%7}, {%8,%9}, {%0,%1,%2,%3};"
        : "+f"(d[0]), "+f"(d[1]), "+f"(d[2]), "+f"(d[3])
        : "r"(a[0]), "r"(a[1]), "r"(a[2]), "r"(a[3]), "r"(b[0]), "r"(b[1]));
}
__device__ __forceinline__ uint32_t f2h2(float a, float b) {
    __half2 h = __floats2half2_rn(a, b);
    return *reinterpret_cast<uint32_t*>(&h);
}
__device__ __forceinline__ uint32_t f2tf32(float x) {
    uint32_t r;
    asm("cvt.rna.tf32.f32 %0, %1;" : "=r"(r) : "f"(x));
    return r;
}
__device__ __forceinline__ void mma_tf32(float d[4], const uint32_t a[4], const uint32_t b[2]) {
    asm volatile(
        "mma.sync.aligned.m16n8k8.row.col.f32.tf32.tf32.f32 "
        "{%0,%1,%2,%3}, {%4,%5,%6,%7}, {%8,%9}, {%0,%1,%2,%3};"
        : "+f"(d[0]), "+f"(d[1]), "+f"(d[2]), "+f"(d[3])
        : "r"(a[0]), "r"(a[1]), "r"(a[2]), "r"(a[3]), "r"(b[0]), "r"(b[1]));
}

// ---------------------------------------------------------------------------
// Prep: split + transpose W into [192][512] fp16 hi/lo
// ---------------------------------------------------------------------------
__global__ void wsplit_kernel(const float* __restrict__ Wq, const float* __restrict__ Wk,
                              const float* __restrict__ Wv) {
    int i = blockIdx.x * 256 + threadIdx.x;
    if (i >= 192 * 512) return;
    int n = i >> 9, k = i & 511;
    const float* W = (n < 64) ? Wq : ((n < 128) ? Wk : Wv);
    float v = W[k * HEAD + (n & 63)];
    __half h = __float2half_rn(v);
    __half l = __float2half_rn(v - __half2float(h));
    g_Wh[i] = __half_as_ushort(h);
    g_Wl[i] = __half_as_ushort(l);
}

// ---------------------------------------------------------------------------
// Kernel 1: QKV projection, fp16-split m16n8k16, double-buffered,
// ONE sync per chunk; A-convert overlapped behind MMAs.
// Block tile 128(M) x 192(N), BK=32. 8 warps = 4M x 2N, warp 32x96.
// ---------------------------------------------------------------------------
#define STAGE_B   51200
#define AH_OFF    0
#define AL_OFF    10240
#define BH_OFF    20480
#define BL_OFF    35840
#define QKV_SMEM  (2 * STAGE_B)   // 102400

__device__ __forceinline__ void qkv_ldg_a(const float* __restrict__ x, int row0,
                                          const int a_r[4], int a_q, int kc, float4 av[4]) {
#pragma unroll
    for (int i = 0; i < 4; i++)
        av[i] = *reinterpret_cast<const float4*>(
            &x[(size_t)(row0 + a_r[i]) * CDIM + kc + a_q * 4]);
}

__device__ __forceinline__ void qkv_cvt_a(char* stage, const int a_r[4], int a_q,
                                          const float4 av[4]) {
#pragma unroll
    for (int i = 0; i < 4; i++) {
        float4 v = av[i];
        uint32_t h0 = f2h2(v.x, v.y), h1 = f2h2(v.z, v.w);
        __half2 hh0 = *reinterpret_cast<__half2*>(&h0);
        __half2 hh1 = *reinterpret_cast<__half2*>(&h1);
        float2 b0 = __half22float2(hh0), b1 = __half22float2(hh1);
        uint32_t l0 = f2h2(v.x - b0.x, v.y - b0.y);
        uint32_t l1 = f2h2(v.z - b1.x, v.w - b1.y);
        int off = a_r[i] * 80 + a_q * 8;
        *reinterpret_cast<uint2*>(stage + AH_OFF + off) = make_uint2(h0, h1);
        *reinterpret_cast<uint2*>(stage + AL_OFF + off) = make_uint2(l0, l1);
    }
}

__device__ __forceinline__ void qkv_cp_b(char* stage, int tid, int kc) {
#pragma unroll
    for (int p = 0; p < 2; p++) {
        const uint16_t* W = p ? g_Wl : g_Wh;
        char* dstb = stage + (p ? BL_OFF : BH_OFF);
#pragma unroll
        for (int s3 = 0; s3 < 3; s3++) {
            int ui = s3 * 256 + tid;
            int n = ui >> 2, ch = ui & 3;
            uint32_t dst;
            asm("{ .reg .u64 t; cvta.to.shared.u64 t, %1; cvt.u32.u64 %0, t; }"
                : "=r"(dst) : "l"(dstb + n * 80 + ch * 16));
            asm volatile("cp.async.ca.shared.global [%0], [%1], 16;"
                         :: "r"(dst), "l"(W + n * 512 + kc + ch * 8));
        }
    }
}

__global__ void __launch_bounds__(256, 1)
qkv_proj_kernel(const float* __restrict__ x) {
    extern __shared__ char smem[];
    const int tid    = threadIdx.x;
    const int lane   = tid & 31;
    const int wid    = tid >> 5;
    const int warp_m = wid & 3;
    const int warp_n = wid >> 2;
    const int gid    = lane >> 2;
    const int tig    = lane & 3;
    const int row0   = blockIdx.x * 128;

    float acc[2][12][4];
#pragma unroll
    for (int mt = 0; mt < 2; mt++)
#pragma unroll
        for (int nt = 0; nt < 12; nt++)
#pragma unroll
            for (int i = 0; i < 4; i++) acc[mt][nt][i] = 0.f;

    float4 av[4];
    const int a_r[4] = {tid >> 3, (256 + tid) >> 3, (512 + tid) >> 3, (768 + tid) >> 3};
    const int a_q = tid & 7;

    // ---- prologue: stage 0 gets B(0) via cp.async and A(0) via LDG+convert ----
    qkv_cp_b(smem, tid, 0);
    asm volatile("cp.async.commit_group;" ::: "memory");
    qkv_ldg_a(x, row0, a_r, a_q, 0, av);
    qkv_cvt_a(smem, a_r, a_q, av);

    for (int c = 0; c < 16; c++) {
        const int cur = (c & 1) * STAGE_B;
        asm volatile("cp.async.wait_group 0;" ::: "memory");
        __syncthreads();   // A(c) converts (prev iter) + B(c) visible to all

        if (c + 1 < 16) {
            const int nxt = ((c + 1) & 1) * STAGE_B;
            const int kc = (c + 1) * 32;
            qkv_ldg_a(x, row0, a_r, a_q, kc, av);   // long-latency, consumed after MMAs
            qkv_cp_b(smem + nxt, tid, kc);
            asm volatile("cp.async.commit_group;" ::: "memory");
        }

        // ---- MMAs for chunk c ----
        const uint32_t* Ah = reinterpret_cast<const uint32_t*>(smem + cur + AH_OFF);
        const uint32_t* Al = reinterpret_cast<const uint32_t*>(smem + cur + AL_OFF);
        const uint32_t* Bh = reinterpret_cast<const uint32_t*>(smem + cur + BH_OFF);
        const uint32_t* Bl = reinterpret_cast<const uint32_t*>(smem + cur + BL_OFF);
#pragma unroll
        for (int kk = 0; kk < 2; kk++) {
            const int kw = kk * 8 + tig;
            uint32_t ah[2][4], al[2][4];
#pragma unroll
            for (int mt = 0; mt < 2; mt++) {
                int r = warp_m * 32 + mt * 16 + gid;
                ah[mt][0] = Ah[r * 20 + kw];
                ah[mt][1] = Ah[(r + 8) * 20 + kw];
                ah[mt][2] = Ah[r * 20 + kw + 4];
                ah[mt][3] = Ah[(r + 8) * 20 + kw + 4];
                al[mt][0] = Al[r * 20 + kw];
                al[mt][1] = Al[(r + 8) * 20 + kw];
                al[mt][2] = Al[r * 20 + kw + 4];
                al[mt][3] = Al[(r + 8) * 20 + kw + 4];
            }
#pragma unroll
            for (int nt = 0; nt < 12; nt++) {
                int n = warp_n * 96 + nt * 8 + gid;
                uint32_t bh[2], bl[2];
                bh[0] = Bh[n * 20 + kw];
                bh[1] = Bh[n * 20 + kw + 4];
                bl[0] = Bl[n * 20 + kw];
                bl[1] = Bl[n * 20 + kw + 4];
#pragma unroll
                for (int mt = 0; mt < 2; mt++) {
                    mma_f16(acc[mt][nt], ah[mt], bh);
                    mma_f16(acc[mt][nt], ah[mt], bl);
                    mma_f16(acc[mt][nt], al[mt], bh);
                }
            }
        }

        // ---- convert A(c+1) into next stage (off critical path) ----
        if (c + 1 < 16)
            qkv_cvt_a(smem + ((c + 1) & 1) * STAGE_B, a_r, a_q, av);
    }

    // ---- writeback as tf32 bit patterns; Q pre-scaled by 0.125 ----
#pragma unroll
    for (int mt = 0; mt < 2; mt++) {
        int r = row0 + warp_m * 32 + mt * 16 + gid;
#pragma unroll
        for (int nt = 0; nt < 12; nt++) {
            int n = warp_n * 96 + nt * 8 + tig * 2;
            uint32_t* dst = (n < 64) ? g_Q : ((n < 128) ? g_K : g_V);
            float s = (n < 64) ? 0.125f : 1.0f;
            int h = n & 63;
            *reinterpret_cast<uint2*>(&dst[(size_t)r * HEAD + h]) =
                make_uint2(f2tf32(acc[mt][nt][0] * s), f2tf32(acc[mt][nt][1] * s));
            *reinterpret_cast<uint2*>(&dst[(size_t)(r + 8) * HEAD + h]) =
                make_uint2(f2tf32(acc[mt][nt][2] * s), f2tf32(acc[mt][nt][3] * s));
        }
    }
}

// ---------------------------------------------------------------------------
// Kernel 2: causal flash attention. Inputs are pre-converted tf32 (Q scaled),
// so tile loads are pure uint4 copies.
// ---------------------------------------------------------------------------
__global__ void __launch_bounds__(128)
attn_kernel(float* __restrict__ out) {
    __shared__ uint32_t KPs[64][68];
    __shared__ uint32_t Vs[64][72];

    const int b = blockIdx.y;
    const int qt = blockIdx.x;
    const int tid = threadIdx.x;
    const int lane = tid & 31;
    const int w = tid >> 5;
    const int gid = lane >> 2;
    const int tig = lane & 3;

    uint32_t qf[8][4];
    {
        const size_t qbase = ((size_t)b * SEQ + (size_t)qt * 64 + w * 16) * HEAD;
#pragma unroll
        for (int kk = 0; kk < 8; kk++) {
            int k = kk * 8 + tig;
            qf[kk][0] = g_Q[qbase + gid * HEAD + k];
            qf[kk][1] = g_Q[qbase + (gid + 8) * HEAD + k];
            qf[kk][2] = g_Q[qbase + gid * HEAD + k + 4];
            qf[kk][3] = g_Q[qbase + (gid + 8) * HEAD + k + 4];
        }
    }

    float m0 = -1e30f, m1 = -1e30f, l0 = 0.f, l1 = 0.f;
    float o[8][4];
#pragma unroll
    for (int nt = 0; nt < 8; nt++)
#pragma unroll
        for (int i = 0; i < 4; i++) o[nt][i] = 0.f;

    for (int j = 0; j <= qt; j++) {
        __syncthreads();
        const size_t kvb = ((size_t)b * SEQ + (size_t)j * 64) * HEAD;
#pragma unroll
        for (int s = 0; s < 8; s++) {
            int idx4 = s * 128 + tid;
            int key = idx4 >> 4;
            int h = (idx4 & 15) * 4;
            *reinterpret_cast<uint4*>(&KPs[key][h]) =
                *reinterpret_cast<const uint4*>(&g_K[kvb + (size_t)key * HEAD + h]);
            *reinterpret_cast<uint4*>(&Vs[key][h]) =
                *reinterpret_cast<const uint4*>(&g_V[kvb + (size_t)key * HEAD + h]);
        }
        __syncthreads();

        float sc[8][4];
#pragma unroll
        for (int nt = 0; nt < 8; nt++)
#pragma unroll
            for (int i = 0; i < 4; i++) sc[nt][i] = 0.f;

#pragma unroll
        for (int kk = 0; kk < 8; kk++) {
            int k = kk * 8 + tig;
#pragma unroll
            for (int nt = 0; nt < 8; nt++) {
                uint32_t bf[2];
                bf[0] = KPs[nt * 8 + gid][k];
                bf[1] = KPs[nt * 8 + gid][k + 4];
                mma_tf32(sc[nt], qf[kk], bf);
            }
        }

        if (j == qt) {
            int q0 = w * 16 + gid, q1 = q0 + 8;
#pragma unroll
            for (int nt = 0; nt < 8; nt++) {
                int kc = nt * 8 + tig * 2;
                if (kc > q0) sc[nt][0] = -1e30f;
                if (kc + 1 > q0) sc[nt][1] = -1e30f;
                if (kc > q1) sc[nt][2] = -1e30f;
                if (kc + 1 > q1) sc[nt][3] = -1e30f;
            }
        }

        float rm0 = -1e30f, rm1 = -1e30f;
#pragma unroll
        for (int nt = 0; nt < 8; nt++) {
            rm0 = fmaxf(rm0, fmaxf(sc[nt][0], sc[nt][1]));
            rm1 = fmaxf(rm1, fmaxf(sc[nt][2], sc[nt][3]));
        }
        rm0 = fmaxf(rm0, __shfl_xor_sync(0xffffffffu, rm0, 1));
        rm0 = fmaxf(rm0, __shfl_xor_sync(0xffffffffu, rm0, 2));
        rm1 = fmaxf(rm1, __shfl_xor_sync(0xffffffffu, rm1, 1));
        rm1 = fmaxf(rm1, __shfl_xor_sync(0xffffffffu, rm1, 2));

        float mn0 = fmaxf(m0, rm0), mn1 = fmaxf(m1, rm1);
        float a0 = __expf(m0 - mn0), a1 = __expf(m1 - mn1);

        float rs0 = 0.f, rs1 = 0.f;
#pragma unroll
        for (int nt = 0; nt < 8; nt++) {
            sc[nt][0] = __expf(sc[nt][0] - mn0);
            sc[nt][1] = __expf(sc[nt][1] - mn0);
            sc[nt][2] = __expf(sc[nt][2] - mn1);
            sc[nt][3] = __expf(sc[nt][3] - mn1);
            rs0 += sc[nt][0] + sc[nt][1];
            rs1 += sc[nt][2] + sc[nt][3];
        }
        rs0 += __shfl_xor_sync(0xffffffffu, rs0, 1);
        rs0 += __shfl_xor_sync(0xffffffffu, rs0, 2);
        rs1 += __shfl_xor_sync(0xffffffffu, rs1, 1);
        rs1 += __shfl_xor_sync(0xffffffffu, rs1, 2);

        l0 = l0 * a0 + rs0;
        l1 = l1 * a1 + rs1;
        m0 = mn0; m1 = mn1;

#pragma unroll
        for (int nt = 0; nt < 8; nt++) {
            o[nt][0] *= a0; o[nt][1] *= a0;
            o[nt][2] *= a1; o[nt][3] *= a1;
        }

        __syncthreads();
#pragma unroll
        for (int nt = 0; nt < 8; nt++) {
            int col = nt * 8 + tig * 2;
            KPs[w * 16 + gid][col] = f2tf32(sc[nt][0]);
            KPs[w * 16 + gid][col + 1] = f2tf32(sc[nt][1]);
            KPs[w * 16 + gid + 8][col] = f2tf32(sc[nt][2]);
            KPs[w * 16 + gid + 8][col + 1] = f2tf32(sc[nt][3]);
        }
        __syncwarp();

#pragma unroll
        for (int kk = 0; kk < 8; kk++) {
            int k = kk * 8 + tig;
            uint32_t af[4];
            af[0] = KPs[w * 16 + gid][k];
            af[1] = KPs[w * 16 + gid + 8][k];
            af[2] = KPs[w * 16 + gid][k + 4];
            af[3] = KPs[w * 16 + gid + 8][k + 4];
#pragma unroll
            for (int nt = 0; nt < 8; nt++) {
                uint32_t bf[2];
                bf[0] = Vs[kk * 8 + tig][nt * 8 + gid];
                bf[1] = Vs[kk * 8 + tig + 4][nt * 8 + gid];
                mma_tf32(o[nt], af, bf);
            }
        }
    }

    float inv0 = 1.f / l0, inv1 = 1.f / l1;
    const size_t ob = ((size_t)b * SEQ + (size_t)qt * 64 + w * 16) * HEAD;
#pragma unroll
    for (int nt = 0; nt < 8; nt++) {
        int h = nt * 8 + tig * 2;
        *reinterpret_cast<float2*>(&out[ob + gid * HEAD + h]) =
            make_float2(o[nt][0] * inv0, o[nt][1] * inv0);
        *reinterpret_cast<float2*>(&out[ob + (gid + 8) * HEAD + h]) =
            make_float2(o[nt][2] * inv1, o[nt][3] * inv1);
    }
}

extern "C" void kernel_launch(void* const* d_in, const int* in_sizes, int n_in,
                              void* d_out, int out_size) {
    (void)in_sizes; (void)n_in; (void)out_size;
    const float* x = (const float*)d_in[0];
    const float* Wq = (const float*)d_in[1];
    const float* Wk = (const float*)d_in[2];
    const float* Wv = (const float*)d_in[3];
    float* out = (float*)d_out;

    cudaFuncSetAttribute(qkv_proj_kernel, cudaFuncAttributeMaxDynamicSharedMemorySize,
                         QKV_SMEM);

    wsplit_kernel<<<(192 * 512 + 255) / 256, 256>>>(Wq, Wk, Wv);
    qkv_proj_kernel<<<MROWS / 128, 256, QKV_SMEM>>>(x);
    attn_kernel<<<dim3(SEQ / 64, BATCH), 128>>>(out);
}

// round 6
// speedup vs baseline: 2.3538x; 1.2140x over previous
#include <cuda_runtime.h>
#include <cuda_fp16.h>
#include <cstdint>

#define BATCH 1024
#define SEQ   256
#define CDIM  512
#define HEAD  64
#define MROWS (BATCH * SEQ)

// Scratch: Q (pre-scaled by 0.125), K, V stored as tf32 bit patterns.
__device__ uint32_t g_Q[(size_t)MROWS * HEAD];
__device__ uint32_t g_K[(size_t)MROWS * HEAD];
__device__ uint32_t g_V[(size_t)MROWS * HEAD];
// Pre-split, pre-transposed weights: [N=192][K=512] fp16 hi/lo.
__device__ uint16_t g_Wh[192 * 512];
__device__ uint16_t g_Wl[192 * 512];

// ---------------------------------------------------------------------------
// mma.sync / ldmatrix helpers (legacy pipe — tcgen05 unavailable here)
// ---------------------------------------------------------------------------
__device__ __forceinline__ void mma_f16(float d[4], const uint32_t a[4], const uint32_t b[2]) {
    asm volatile(
        "mma.sync.aligned.m16n8k16.row.col.f32.f16.f16.f32 "
        "{%0,%1,%2,%3}, {%4,%5,%6,%7}, {%8,%9}, {%0,%1,%2,%3};"
        : "+f"(d[0]), "+f"(d[1]), "+f"(d[2]), "+f"(d[3])
        : "r"(a[0]), "r"(a[1]), "r"(a[2]), "r"(a[3]), "r"(b[0]), "r"(b[1]));
}
__device__ __forceinline__ void ldsm_x4(uint32_t& r0, uint32_t& r1, uint32_t& r2,
                                        uint32_t& r3, uint32_t addr) {
    asm volatile("ldmatrix.sync.aligned.m8n8.x4.shared.b16 {%0,%1,%2,%3}, [%4];"
                 : "=r"(r0), "=r"(r1), "=r"(r2), "=r"(r3) : "r"(addr));
}
__device__ __forceinline__ uint32_t f2h2(float a, float b) {
    __half2 h = __floats2half2_rn(a, b);
    return *reinterpret_cast<uint32_t*>(&h);
}
__device__ __forceinline__ uint32_t f2tf32(float x) {
    uint32_t r;
    asm("cvt.rna.tf32.f32 %0, %1;" : "=r"(r) : "f"(x));
    return r;
}
__device__ __forceinline__ void mma_tf32(float d[4], const uint32_t a[4], const uint32_t b[2]) {
    asm volatile(
        "mma.sync.aligned.m16n8k8.row.col.f32.tf32.tf32.f32 "
        "{%0,%1,%2,%3}, {%4,%5,%6,%7}, {%8,%9}, {%0,%1,%2,%3};"
        : "+f"(d[0]), "+f"(d[1]), "+f"(d[2]), "+f"(d[3])
        : "r"(a[0]), "r"(a[1]), "r"(a[2]), "r"(a[3]), "r"(b[0]), "r"(b[1]));
}
__device__ __forceinline__ uint32_t smem_u32(const void* p) {
    uint32_t a;
    asm("{ .reg .u64 t; cvta.to.shared.u64 t, %1; cvt.u32.u64 %0, t; }" : "=r"(a) : "l"(p));
    return a;
}

// ---------------------------------------------------------------------------
// Prep: split + transpose W into [192][512] fp16 hi/lo
// ---------------------------------------------------------------------------
__global__ void wsplit_kernel(const float* __restrict__ Wq, const float* __restrict__ Wk,
                              const float* __restrict__ Wv) {
    int i = blockIdx.x * 256 + threadIdx.x;
    if (i >= 192 * 512) return;
    int n = i >> 9, k = i & 511;
    const float* W = (n < 64) ? Wq : ((n < 128) ? Wk : Wv);
    float v = W[k * HEAD + (n & 63)];
    __half h = __float2half_rn(v);
    __half l = __float2half_rn(v - __half2float(h));
    g_Wh[i] = __half_as_ushort(h);
    g_Wl[i] = __half_as_ushort(l);
}

// ---------------------------------------------------------------------------
// Kernel 1: QKV projection. 2-term fp16 split: D = Ah*(Bh+Bl).
// Block tile 128(M) x 192(N), BK=32. 8 warps = 4M x 2N, warp 32x96.
// All fragment loads via ldmatrix.x4 (B: hi+lo in one x4 via lane addressing).
// ---------------------------------------------------------------------------
#define AH_OFF    0
#define BH_OFF    10240
#define BL_OFF    25600
#define STAGE_B   40960
#define QKV_SMEM  (2 * STAGE_B)   // 81920

__device__ __forceinline__ void qkv_ldg_a(const float* __restrict__ x, int row0,
                                          const int a_r[4], int a_q, int kc, float4 av[4]) {
#pragma unroll
    for (int i = 0; i < 4; i++)
        av[i] = *reinterpret_cast<const float4*>(
            &x[(size_t)(row0 + a_r[i]) * CDIM + kc + a_q * 4]);
}

__device__ __forceinline__ void qkv_cvt_a(char* stage, const int a_r[4], int a_q,
                                          const float4 av[4]) {
#pragma unroll
    for (int i = 0; i < 4; i++) {
        float4 v = av[i];
        uint32_t h0 = f2h2(v.x, v.y), h1 = f2h2(v.z, v.w);
        *reinterpret_cast<uint2*>(stage + AH_OFF + a_r[i] * 80 + a_q * 8) =
            make_uint2(h0, h1);
    }
}

__device__ __forceinline__ void qkv_cp_b(char* stage, int tid, int kc) {
#pragma unroll
    for (int p = 0; p < 2; p++) {
        const uint16_t* W = p ? g_Wl : g_Wh;
        char* dstb = stage + (p ? BL_OFF : BH_OFF);
#pragma unroll
        for (int s3 = 0; s3 < 3; s3++) {
            int ui = s3 * 256 + tid;
            int n = ui >> 2, ch = ui & 3;
            uint32_t dst;
            asm("{ .reg .u64 t; cvta.to.shared.u64 t, %1; cvt.u32.u64 %0, t; }"
                : "=r"(dst) : "l"(dstb + n * 80 + ch * 16));
            asm volatile("cp.async.ca.shared.global [%0], [%1], 16;"
                         :: "r"(dst), "l"(W + n * 512 + kc + ch * 8));
        }
    }
}

__global__ void __launch_bounds__(256, 1)
qkv_proj_kernel(const float* __restrict__ x) {
    extern __shared__ char smem[];
    const uint32_t smem_b = smem_u32(smem);
    const int tid    = threadIdx.x;
    const int lane   = tid & 31;
    const int wid    = tid >> 5;
    const int warp_m = wid & 3;
    const int warp_n = wid >> 2;
    const int gid    = lane >> 2;
    const int tig    = lane & 3;
    const int row0   = blockIdx.x * 128;

    // ldmatrix lane-address bases (byte offsets within a stage)
    // A frag (m16k16): lanes 0-7 -> M00 rows, 8-15 -> M10, 16-23 -> M01, 24-31 -> M11
    const uint32_t a_base =
        (uint32_t)((warp_m * 32 + (lane & 15)) * 80 + (lane >> 4) * 16);
    // B frag x4: matrices [Bh k0-7, Bh k8-15, Bl k0-7, Bl k8-15]
    const uint32_t b_base =
        (uint32_t)(((lane < 16) ? BH_OFF : BL_OFF) +
                   (warp_n * 96 + (lane & 7)) * 80 + ((lane >> 3) & 1) * 16);

    float acc[2][12][4];
#pragma unroll
    for (int mt = 0; mt < 2; mt++)
#pragma unroll
        for (int nt = 0; nt < 12; nt++)
#pragma unroll
            for (int i = 0; i < 4; i++) acc[mt][nt][i] = 0.f;

    float4 av[4];
    const int a_r[4] = {tid >> 3, (256 + tid) >> 3, (512 + tid) >> 3, (768 + tid) >> 3};
    const int a_q = tid & 7;

    // ---- prologue ----
    qkv_cp_b(smem, tid, 0);
    asm volatile("cp.async.commit_group;" ::: "memory");
    qkv_ldg_a(x, row0, a_r, a_q, 0, av);
    qkv_cvt_a(smem, a_r, a_q, av);

    for (int c = 0; c < 16; c++) {
        const int cur = (c & 1) * STAGE_B;
        asm volatile("cp.async.wait_group 0;" ::: "memory");
        __syncthreads();

        if (c + 1 < 16) {
            const int nxt = ((c + 1) & 1) * STAGE_B;
            const int kc = (c + 1) * 32;
            qkv_ldg_a(x, row0, a_r, a_q, kc, av);
            qkv_cp_b(smem + nxt, tid, kc);
            asm volatile("cp.async.commit_group;" ::: "memory");
        }

        // ---- MMAs for chunk c (ldmatrix fragments) ----
        const uint32_t sstage = smem_b + cur;
#pragma unroll
        for (int kk = 0; kk < 2; kk++) {
            uint32_t ah[2][4];
            ldsm_x4(ah[0][0], ah[0][1], ah[0][2], ah[0][3],
                    sstage + AH_OFF + a_base + kk * 32);
            ldsm_x4(ah[1][0], ah[1][1], ah[1][2], ah[1][3],
                    sstage + AH_OFF + a_base + 1280 + kk * 32);
#pragma unroll
            for (int nt = 0; nt < 12; nt++) {
                uint32_t bb[4];
                ldsm_x4(bb[0], bb[1], bb[2], bb[3],
                        sstage + b_base + nt * 640 + kk * 32);
                mma_f16(acc[0][nt], ah[0], &bb[0]);
                mma_f16(acc[1][nt], ah[1], &bb[0]);
                mma_f16(acc[0][nt], ah[0], &bb[2]);
                mma_f16(acc[1][nt], ah[1], &bb[2]);
            }
        }

        if (c + 1 < 16)
            qkv_cvt_a(smem + ((c + 1) & 1) * STAGE_B, a_r, a_q, av);
    }

    // ---- writeback as tf32 bit patterns; Q pre-scaled by 0.125 ----
#pragma unroll
    for (int mt = 0; mt < 2; mt++) {
        int r = row0 + warp_m * 32 + mt * 16 + gid;
#pragma unroll
        for (int nt = 0; nt < 12; nt++) {
            int n = warp_n * 96 + nt * 8 + tig * 2;
            uint32_t* dst = (n < 64) ? g_Q : ((n < 128) ? g_K : g_V);
            float s = (n < 64) ? 0.125f : 1.0f;
            int h = n & 63;
            *reinterpret_cast<uint2*>(&dst[(size_t)r * HEAD + h]) =
                make_uint2(f2tf32(acc[mt][nt][0] * s), f2tf32(acc[mt][nt][1] * s));
            *reinterpret_cast<uint2*>(&dst[(size_t)(r + 8) * HEAD + h]) =
                make_uint2(f2tf32(acc[mt][nt][2] * s), f2tf32(acc[mt][nt][3] * s));
        }
    }
}

// ---------------------------------------------------------------------------
// Kernel 2: causal flash attention (tf32 inputs pre-converted; heavy tiles first)
// ---------------------------------------------------------------------------
__global__ void __launch_bounds__(128)
attn_kernel(float* __restrict__ out) {
    __shared__ uint32_t KPs[64][68];
    __shared__ uint32_t Vs[64][72];

    const int b = blockIdx.y;
    const int qt = (gridDim.x - 1) - blockIdx.x;  // heavy (qt=3) blocks launch first
    const int tid = threadIdx.x;
    const int lane = tid & 31;
    const int w = tid >> 5;
    const int gid = lane >> 2;
    const int tig = lane & 3;

    uint32_t qf[8][4];
    {
        const size_t qbase = ((size_t)b * SEQ + (size_t)qt * 64 + w * 16) * HEAD;
#pragma unroll
        for (int kk = 0; kk < 8; kk++) {
            int k = kk * 8 + tig;
            qf[kk][0] = g_Q[qbase + gid * HEAD + k];
            qf[kk][1] = g_Q[qbase + (gid + 8) * HEAD + k];
            qf[kk][2] = g_Q[qbase + gid * HEAD + k + 4];
            qf[kk][3] = g_Q[qbase + (gid + 8) * HEAD + k + 4];
        }
    }

    float m0 = -1e30f, m1 = -1e30f, l0 = 0.f, l1 = 0.f;
    float o[8][4];
#pragma unroll
    for (int nt = 0; nt < 8; nt++)
#pragma unroll
        for (int i = 0; i < 4; i++) o[nt][i] = 0.f;

    for (int j = 0; j <= qt; j++) {
        __syncthreads();
        const size_t kvb = ((size_t)b * SEQ + (size_t)j * 64) * HEAD;
#pragma unroll
        for (int s = 0; s < 8; s++) {
            int idx4 = s * 128 + tid;
            int key = idx4 >> 4;
            int h = (idx4 & 15) * 4;
            *reinterpret_cast<uint4*>(&KPs[key][h]) =
                *reinterpret_cast<const uint4*>(&g_K[kvb + (size_t)key * HEAD + h]);
            *reinterpret_cast<uint4*>(&Vs[key][h]) =
                *reinterpret_cast<const uint4*>(&g_V[kvb + (size_t)key * HEAD + h]);
        }
        __syncthreads();

        float sc[8][4];
#pragma unroll
        for (int nt = 0; nt < 8; nt++)
#pragma unroll
            for (int i = 0; i < 4; i++) sc[nt][i] = 0.f;

#pragma unroll
        for (int kk = 0; kk < 8; kk++) {
            int k = kk * 8 + tig;
#pragma unroll
            for (int nt = 0; nt < 8; nt++) {
                uint32_t bf[2];
                bf[0] = KPs[nt * 8 + gid][k];
                bf[1] = KPs[nt * 8 + gid][k + 4];
                mma_tf32(sc[nt], qf[kk], bf);
            }
        }

        if (j == qt) {
            int q0 = w * 16 + gid, q1 = q0 + 8;
#pragma unroll
            for (int nt = 0; nt < 8; nt++) {
                int kc = nt * 8 + tig * 2;
                if (kc > q0) sc[nt][0] = -1e30f;
                if (kc + 1 > q0) sc[nt][1] = -1e30f;
                if (kc > q1) sc[nt][2] = -1e30f;
                if (kc + 1 > q1) sc[nt][3] = -1e30f;
            }
        }

        float rm0 = -1e30f, rm1 = -1e30f;
#pragma unroll
        for (int nt = 0; nt < 8; nt++) {
            rm0 = fmaxf(rm0, fmaxf(sc[nt][0], sc[nt][1]));
            rm1 = fmaxf(rm1, fmaxf(sc[nt][2], sc[nt][3]));
        }
        rm0 = fmaxf(rm0, __shfl_xor_sync(0xffffffffu, rm0, 1));
        rm0 = fmaxf(rm0, __shfl_xor_sync(0xffffffffu, rm0, 2));
        rm1 = fmaxf(rm1, __shfl_xor_sync(0xffffffffu, rm1, 1));
        rm1 = fmaxf(rm1, __shfl_xor_sync(0xffffffffu, rm1, 2));

        float mn0 = fmaxf(m0, rm0), mn1 = fmaxf(m1, rm1);
        float a0 = __expf(m0 - mn0), a1 = __expf(m1 - mn1);

        float rs0 = 0.f, rs1 = 0.f;
#pragma unroll
        for (int nt = 0; nt < 8; nt++) {
            sc[nt][0] = __expf(sc[nt][0] - mn0);
            sc[nt][1] = __expf(sc[nt][1] - mn0);
            sc[nt][2] = __expf(sc[nt][2] - mn1);
            sc[nt][3] = __expf(sc[nt][3] - mn1);
            rs0 += sc[nt][0] + sc[nt][1];
            rs1 += sc[nt][2] + sc[nt][3];
        }
        rs0 += __shfl_xor_sync(0xffffffffu, rs0, 1);
        rs0 += __shfl_xor_sync(0xffffffffu, rs0, 2);
        rs1 += __shfl_xor_sync(0xffffffffu, rs1, 1);
        rs1 += __shfl_xor_sync(0xffffffffu, rs1, 2);

        l0 = l0 * a0 + rs0;
        l1 = l1 * a1 + rs1;
        m0 = mn0; m1 = mn1;

#pragma unroll
        for (int nt = 0; nt < 8; nt++) {
            o[nt][0] *= a0; o[nt][1] *= a0;
            o[nt][2] *= a1; o[nt][3] *= a1;
        }

        __syncthreads();
#pragma unroll
        for (int nt = 0; nt < 8; nt++) {
            int col = nt * 8 + tig * 2;
            KPs[w * 16 + gid][col] = f2tf32(sc[nt][0]);
            KPs[w * 16 + gid][col + 1] = f2tf32(sc[nt][1]);
            KPs[w * 16 + gid + 8][col] = f2tf32(sc[nt][2]);
            KPs[w * 16 + gid + 8][col + 1] = f2tf32(sc[nt][3]);
        }
        __syncwarp();

#pragma unroll
        for (int kk = 0; kk < 8; kk++) {
            int k = kk * 8 + tig;
            uint32_t af[4];
            af[0] = KPs[w * 16 + gid][k];
            af[1] = KPs[w * 16 + gid + 8][k];
            af[2] = KPs[w * 16 + gid][k + 4];
            af[3] = KPs[w * 16 + gid + 8][k + 4];
#pragma unroll
            for (int nt = 0; nt < 8; nt++) {
                uint32_t bf[2];
                bf[0] = Vs[kk * 8 + tig][nt * 8 + gid];
                bf[1] = Vs[kk * 8 + tig + 4][nt * 8 + gid];
                mma_tf32(o[nt], af, bf);
            }
        }
    }

    float inv0 = 1.f / l0, inv1 = 1.f / l1;
    const size_t ob = ((size_t)b * SEQ + (size_t)qt * 64 + w * 16) * HEAD;
#pragma unroll
    for (int nt = 0; nt < 8; nt++) {
        int h = nt * 8 + tig * 2;
        *reinterpret_cast<float2*>(&out[ob + gid * HEAD + h]) =
            make_float2(o[nt][0] * inv0, o[nt][1] * inv0);
        *reinterpret_cast<float2*>(&out[ob + (gid + 8) * HEAD + h]) =
            make_float2(o[nt][2] * inv1, o[nt][3] * inv1);
    }
}

extern "C" void kernel_launch(void* const* d_in, const int* in_sizes, int n_in,
                              void* d_out, int out_size) {
    (void)in_sizes; (void)n_in; (void)out_size;
    const float* x = (const float*)d_in[0];
    const float* Wq = (const float*)d_in[1];
    const float* Wk = (const float*)d_in[2];
    const float* Wv = (const float*)d_in[3];
    float* out = (float*)d_out;

    cudaFuncSetAttribute(qkv_proj_kernel, cudaFuncAttributeMaxDynamicSharedMemorySize,
                         QKV_SMEM);

    wsplit_kernel<<<(192 * 512 + 255) / 256, 256>>>(Wq, Wk, Wv);
    qkv_proj_kernel<<<MROWS / 128, 256, QKV_SMEM>>>(x);
    attn_kernel<<<dim3(SEQ / 64, BATCH), 128>>>(out);
}

// round 7
// speedup vs baseline: 2.4444x; 1.0385x over previous
#include <cuda_runtime.h>
#include <cuda_fp16.h>
#include <cstdint>

#define BATCH 1024
#define SEQ   256
#define CDIM  512
#define HEAD  64
#define MROWS (BATCH * SEQ)

// Scratch: Q (pre-scaled by 0.125), K, V stored as tf32 bit patterns.
__device__ uint32_t g_Q[(size_t)MROWS * HEAD];
__device__ uint32_t g_K[(size_t)MROWS * HEAD];
__device__ uint32_t g_V[(size_t)MROWS * HEAD];
// Pre-split, pre-transposed weights: [N=192][K=512] fp16 hi/lo.
__device__ uint16_t g_Wh[192 * 512];
__device__ uint16_t g_Wl[192 * 512];

// ---------------------------------------------------------------------------
// mma.sync / ldmatrix helpers (legacy pipe — tcgen05 unavailable here)
// ---------------------------------------------------------------------------
__device__ __forceinline__ void mma_f16(float d[4], const uint32_t a[4], const uint32_t b[2]) {
    asm volatile(
        "mma.sync.aligned.m16n8k16.row.col.f32.f16.f16.f32 "
        "{%0,%1,%2,%3}, {%4,%5,%6,%7}, {%8,%9}, {%0,%1,%2,%3};"
        : "+f"(d[0]), "+f"(d[1]), "+f"(d[2]), "+f"(d[3])
        : "r"(a[0]), "r"(a[1]), "r"(a[2]), "r"(a[3]), "r"(b[0]), "r"(b[1]));
}
__device__ __forceinline__ void ldsm_x4(uint32_t& r0, uint32_t& r1, uint32_t& r2,
                                        uint32_t& r3, uint32_t addr) {
    asm volatile("ldmatrix.sync.aligned.m8n8.x4.shared.b16 {%0,%1,%2,%3}, [%4];"
                 : "=r"(r0), "=r"(r1), "=r"(r2), "=r"(r3) : "r"(addr));
}
__device__ __forceinline__ uint32_t f2h2(float a, float b) {
    __half2 h = __floats2half2_rn(a, b);
    return *reinterpret_cast<uint32_t*>(&h);
}
__device__ __forceinline__ uint32_t f2tf32(float x) {
    uint32_t r;
    asm("cvt.rna.tf32.f32 %0, %1;" : "=r"(r) : "f"(x));
    return r;
}
__device__ __forceinline__ void mma_tf32(float d[4], const uint32_t a[4], const uint32_t b[2]) {
    asm volatile(
        "mma.sync.aligned.m16n8k8.row.col.f32.tf32.tf32.f32 "
        "{%0,%1,%2,%3}, {%4,%5,%6,%7}, {%8,%9}, {%0,%1,%2,%3};"
        : "+f"(d[0]), "+f"(d[1]), "+f"(d[2]), "+f"(d[3])
        : "r"(a[0]), "r"(a[1]), "r"(a[2]), "r"(a[3]), "r"(b[0]), "r"(b[1]));
}
__device__ __forceinline__ uint32_t smem_u32(const void* p) {
    uint32_t a;
    asm("{ .reg .u64 t; cvta.to.shared.u64 t, %1; cvt.u32.u64 %0, t; }" : "=r"(a) : "l"(p));
    return a;
}

// ---------------------------------------------------------------------------
// Prep: split + transpose W into [192][512] fp16 hi/lo
// ---------------------------------------------------------------------------
__global__ void wsplit_kernel(const float* __restrict__ Wq, const float* __restrict__ Wk,
                              const float* __restrict__ Wv) {
    int i = blockIdx.x * 256 + threadIdx.x;
    if (i >= 192 * 512) return;
    int n = i >> 9, k = i & 511;
    const float* W = (n < 64) ? Wq : ((n < 128) ? Wk : Wv);
    float v = W[k * HEAD + (n & 63)];
    __half h = __float2half_rn(v);
    __half l = __float2half_rn(v - __half2float(h));
    g_Wh[i] = __half_as_ushort(h);
    g_Wl[i] = __half_as_ushort(l);
}

// ---------------------------------------------------------------------------
// Kernel 1: QKV projection. 2-term fp16 split: D = Ah*(Bh+Bl).
// Block tile 128(M) x 192(N), BK=32. 512 threads: 16 warps = 4M x 4N,
// warp tile 32x48 (48 acc regs -> fits 128-reg budget, 4 warps/SMSP).
// ---------------------------------------------------------------------------
#define AH_OFF    0
#define BH_OFF    10240
#define BL_OFF    25600
#define STAGE_B   40960
#define QKV_SMEM  (2 * STAGE_B)   // 81920

__device__ __forceinline__ void qkv_ldg_a(const float* __restrict__ x, int row0,
                                          const int a_r[2], int a_q, int kc, float4 av[2]) {
#pragma unroll
    for (int i = 0; i < 2; i++)
        av[i] = *reinterpret_cast<const float4*>(
            &x[(size_t)(row0 + a_r[i]) * CDIM + kc + a_q * 4]);
}

__device__ __forceinline__ void qkv_cvt_a(char* stage, const int a_r[2], int a_q,
                                          const float4 av[2]) {
#pragma unroll
    for (int i = 0; i < 2; i++) {
        float4 v = av[i];
        uint32_t h0 = f2h2(v.x, v.y), h1 = f2h2(v.z, v.w);
        *reinterpret_cast<uint2*>(stage + AH_OFF + a_r[i] * 80 + a_q * 8) =
            make_uint2(h0, h1);
    }
}

__device__ __forceinline__ void qkv_cp_b(char* stage, int tid, int kc) {
    // 1536 uint4 slots total: [0,768) = hi, [768,1536) = lo; 512 threads x 3.
#pragma unroll
    for (int s3 = 0; s3 < 3; s3++) {
        int ui = s3 * 512 + tid;
        int p = ui >> 9 >= 1 && ui >= 768;           // lo if ui >= 768
        int li = ui - (ui >= 768 ? 768 : 0);
        const uint16_t* W = (ui >= 768) ? g_Wl : g_Wh;
        char* dstb = stage + ((ui >= 768) ? BL_OFF : BH_OFF);
        (void)p;
        int n = li >> 2, ch = li & 3;
        uint32_t dst;
        asm("{ .reg .u64 t; cvta.to.shared.u64 t, %1; cvt.u32.u64 %0, t; }"
            : "=r"(dst) : "l"(dstb + n * 80 + ch * 16));
        asm volatile("cp.async.ca.shared.global [%0], [%1], 16;"
                     :: "r"(dst), "l"(W + n * 512 + kc + ch * 8));
    }
}

__global__ void __launch_bounds__(512, 1)
qkv_proj_kernel(const float* __restrict__ x) {
    extern __shared__ char smem[];
    const uint32_t smem_b = smem_u32(smem);
    const int tid    = threadIdx.x;
    const int lane   = tid & 31;
    const int wid    = tid >> 5;
    const int warp_m = wid & 3;    // 0..3 -> M rows
    const int warp_n = wid >> 2;   // 0..3 -> N cols (x48)
    const int gid    = lane >> 2;
    const int tig    = lane & 3;
    const int row0   = blockIdx.x * 128;

    // ldmatrix lane-address bases (byte offsets within a stage)
    const uint32_t a_base =
        (uint32_t)((warp_m * 32 + (lane & 15)) * 80 + (lane >> 4) * 16);
    // B frag x4: [Bh k0-7, Bh k8-15, Bl k0-7, Bl k8-15]
    const uint32_t b_base =
        (uint32_t)(((lane < 16) ? BH_OFF : BL_OFF) +
                   (warp_n * 48 + (lane & 7)) * 80 + ((lane >> 3) & 1) * 16);

    float acc[2][6][4];
#pragma unroll
    for (int mt = 0; mt < 2; mt++)
#pragma unroll
        for (int nt = 0; nt < 6; nt++)
#pragma unroll
            for (int i = 0; i < 4; i++) acc[mt][nt][i] = 0.f;

    float4 av[2];
    const int a_r[2] = {tid >> 3, (512 + tid) >> 3};
    const int a_q = tid & 7;

    // ---- prologue ----
    qkv_cp_b(smem, tid, 0);
    asm volatile("cp.async.commit_group;" ::: "memory");
    qkv_ldg_a(x, row0, a_r, a_q, 0, av);
    qkv_cvt_a(smem, a_r, a_q, av);

    for (int c = 0; c < 16; c++) {
        const int cur = (c & 1) * STAGE_B;
        asm volatile("cp.async.wait_group 0;" ::: "memory");
        __syncthreads();

        if (c + 1 < 16) {
            const int nxt = ((c + 1) & 1) * STAGE_B;
            const int kc = (c + 1) * 32;
            qkv_ldg_a(x, row0, a_r, a_q, kc, av);
            qkv_cp_b(smem + nxt, tid, kc);
            asm volatile("cp.async.commit_group;" ::: "memory");
        }

        // ---- MMAs for chunk c (ldmatrix fragments) ----
        const uint32_t sstage = smem_b + cur;
#pragma unroll
        for (int kk = 0; kk < 2; kk++) {
            uint32_t ah[2][4];
            ldsm_x4(ah[0][0], ah[0][1], ah[0][2], ah[0][3],
                    sstage + AH_OFF + a_base + kk * 32);
            ldsm_x4(ah[1][0], ah[1][1], ah[1][2], ah[1][3],
                    sstage + AH_OFF + a_base + 1280 + kk * 32);
#pragma unroll
            for (int nt = 0; nt < 6; nt++) {
                uint32_t bb[4];
                ldsm_x4(bb[0], bb[1], bb[2], bb[3],
                        sstage + b_base + nt * 640 + kk * 32);
                mma_f16(acc[0][nt], ah[0], &bb[0]);
                mma_f16(acc[1][nt], ah[1], &bb[0]);
                mma_f16(acc[0][nt], ah[0], &bb[2]);
                mma_f16(acc[1][nt], ah[1], &bb[2]);
            }
        }

        if (c + 1 < 16)
            qkv_cvt_a(smem + ((c + 1) & 1) * STAGE_B, a_r, a_q, av);
    }

    // ---- writeback as tf32 bit patterns; Q pre-scaled by 0.125 ----
#pragma unroll
    for (int mt = 0; mt < 2; mt++) {
        int r = row0 + warp_m * 32 + mt * 16 + gid;
#pragma unroll
        for (int nt = 0; nt < 6; nt++) {
            int n = warp_n * 48 + nt * 8 + tig * 2;
            uint32_t* dst = (n < 64) ? g_Q : ((n < 128) ? g_K : g_V);
            float s = (n < 64) ? 0.125f : 1.0f;
            int h = n & 63;
            *reinterpret_cast<uint2*>(&dst[(size_t)r * HEAD + h]) =
                make_uint2(f2tf32(acc[mt][nt][0] * s), f2tf32(acc[mt][nt][1] * s));
            *reinterpret_cast<uint2*>(&dst[(size_t)(r + 8) * HEAD + h]) =
                make_uint2(f2tf32(acc[mt][nt][2] * s), f2tf32(acc[mt][nt][3] * s));
        }
    }
}

// ---------------------------------------------------------------------------
// Kernel 2: causal flash attention (tf32 inputs pre-converted; heavy tiles
// first; launch_bounds(128,4) to lift the 130-reg -> 3-block occupancy cap)
// ---------------------------------------------------------------------------
__global__ void __launch_bounds__(128, 4)
attn_kernel(float* __restrict__ out) {
    __shared__ uint32_t KPs[64][68];
    __shared__ uint32_t Vs[64][72];

    const int b = blockIdx.y;
    const int qt = (gridDim.x - 1) - blockIdx.x;  // heavy (qt=3) blocks launch first
    const int tid = threadIdx.x;
    const int lane = tid & 31;
    const int w = tid >> 5;
    const int gid = lane >> 2;
    const int tig = lane & 3;

    uint32_t qf[8][4];
    {
        const size_t qbase = ((size_t)b * SEQ + (size_t)qt * 64 + w * 16) * HEAD;
#pragma unroll
        for (int kk = 0; kk < 8; kk++) {
            int k = kk * 8 + tig;
            qf[kk][0] = g_Q[qbase + gid * HEAD + k];
            qf[kk][1] = g_Q[qbase + (gid + 8) * HEAD + k];
            qf[kk][2] = g_Q[qbase + gid * HEAD + k + 4];
            qf[kk][3] = g_Q[qbase + (gid + 8) * HEAD + k + 4];
        }
    }

    float m0 = -1e30f, m1 = -1e30f, l0 = 0.f, l1 = 0.f;
    float o[8][4];
#pragma unroll
    for (int nt = 0; nt < 8; nt++)
#pragma unroll
        for (int i = 0; i < 4; i++) o[nt][i] = 0.f;

    for (int j = 0; j <= qt; j++) {
        __syncthreads();
        const size_t kvb = ((size_t)b * SEQ + (size_t)j * 64) * HEAD;
#pragma unroll
        for (int s = 0; s < 8; s++) {
            int idx4 = s * 128 + tid;
            int key = idx4 >> 4;
            int h = (idx4 & 15) * 4;
            *reinterpret_cast<uint4*>(&KPs[key][h]) =
                *reinterpret_cast<const uint4*>(&g_K[kvb + (size_t)key * HEAD + h]);
            *reinterpret_cast<uint4*>(&Vs[key][h]) =
                *reinterpret_cast<const uint4*>(&g_V[kvb + (size_t)key * HEAD + h]);
        }
        __syncthreads();

        float sc[8][4];
#pragma unroll
        for (int nt = 0; nt < 8; nt++)
#pragma unroll
            for (int i = 0; i < 4; i++) sc[nt][i] = 0.f;

#pragma unroll
        for (int kk = 0; kk < 8; kk++) {
            int k = kk * 8 + tig;
#pragma unroll
            for (int nt = 0; nt < 8; nt++) {
                uint32_t bf[2];
                bf[0] = KPs[nt * 8 + gid][k];
                bf[1] = KPs[nt * 8 + gid][k + 4];
                mma_tf32(sc[nt], qf[kk], bf);
            }
        }

        if (j == qt) {
            int q0 = w * 16 + gid, q1 = q0 + 8;
#pragma unroll
            for (int nt = 0; nt < 8; nt++) {
                int kc = nt * 8 + tig * 2;
                if (kc > q0) sc[nt][0] = -1e30f;
                if (kc + 1 > q0) sc[nt][1] = -1e30f;
                if (kc > q1) sc[nt][2] = -1e30f;
                if (kc + 1 > q1) sc[nt][3] = -1e30f;
            }
        }

        float rm0 = -1e30f, rm1 = -1e30f;
#pragma unroll
        for (int nt = 0; nt < 8; nt++) {
            rm0 = fmaxf(rm0, fmaxf(sc[nt][0], sc[nt][1]));
            rm1 = fmaxf(rm1, fmaxf(sc[nt][2], sc[nt][3]));
        }
        rm0 = fmaxf(rm0, __shfl_xor_sync(0xffffffffu, rm0, 1));
        rm0 = fmaxf(rm0, __shfl_xor_sync(0xffffffffu, rm0, 2));
        rm1 = fmaxf(rm1, __shfl_xor_sync(0xffffffffu, rm1, 1));
        rm1 = fmaxf(rm1, __shfl_xor_sync(0xffffffffu, rm1, 2));

        float mn0 = fmaxf(m0, rm0), mn1 = fmaxf(m1, rm1);
        float a0 = __expf(m0 - mn0), a1 = __expf(m1 - mn1);

        float rs0 = 0.f, rs1 = 0.f;
#pragma unroll
        for (int nt = 0; nt < 8; nt++) {
            sc[nt][0] = __expf(sc[nt][0] - mn0);
            sc[nt][1] = __expf(sc[nt][1] - mn0);
            sc[nt][2] = __expf(sc[nt][2] - mn1);
            sc[nt][3] = __expf(sc[nt][3] - mn1);
            rs0 += sc[nt][0] + sc[nt][1];
            rs1 += sc[nt][2] + sc[nt][3];
        }
        rs0 += __shfl_xor_sync(0xffffffffu, rs0, 1);
        rs0 += __shfl_xor_sync(0xffffffffu, rs0, 2);
        rs1 += __shfl_xor_sync(0xffffffffu, rs1, 1);
        rs1 += __shfl_xor_sync(0xffffffffu, rs1, 2);

        l0 = l0 * a0 + rs0;
        l1 = l1 * a1 + rs1;
        m0 = mn0; m1 = mn1;

#pragma unroll
        for (int nt = 0; nt < 8; nt++) {
            o[nt][0] *= a0; o[nt][1] *= a0;
            o[nt][2] *= a1; o[nt][3] *= a1;
        }

        __syncthreads();
#pragma unroll
        for (int nt = 0; nt < 8; nt++) {
            int col = nt * 8 + tig * 2;
            KPs[w * 16 + gid][col] = f2tf32(sc[nt][0]);
            KPs[w * 16 + gid][col + 1] = f2tf32(sc[nt][1]);
            KPs[w * 16 + gid + 8][col] = f2tf32(sc[nt][2]);
            KPs[w * 16 + gid + 8][col + 1] = f2tf32(sc[nt][3]);
        }
        __syncwarp();

#pragma unroll
        for (int kk = 0; kk < 8; kk++) {
            int k = kk * 8 + tig;
            uint32_t af[4];
            af[0] = KPs[w * 16 + gid][k];
            af[1] = KPs[w * 16 + gid + 8][k];
            af[2] = KPs[w * 16 + gid][k + 4];
            af[3] = KPs[w * 16 + gid + 8][k + 4];
#pragma unroll
            for (int nt = 0; nt < 8; nt++) {
                uint32_t bf[2];
                bf[0] = Vs[kk * 8 + tig][nt * 8 + gid];
                bf[1] = Vs[kk * 8 + tig + 4][nt * 8 + gid];
                mma_tf32(o[nt], af, bf);
            }
        }
    }

    float inv0 = 1.f / l0, inv1 = 1.f / l1;
    const size_t ob = ((size_t)b * SEQ + (size_t)qt * 64 + w * 16) * HEAD;
#pragma unroll
    for (int nt = 0; nt < 8; nt++) {
        int h = nt * 8 + tig * 2;
        *reinterpret_cast<float2*>(&out[ob + gid * HEAD + h]) =
            make_float2(o[nt][0] * inv0, o[nt][1] * inv0);
        *reinterpret_cast<float2*>(&out[ob + (gid + 8) * HEAD + h]) =
            make_float2(o[nt][2] * inv1, o[nt][3] * inv1);
    }
}

extern "C" void kernel_launch(void* const* d_in, const int* in_sizes, int n_in,
                              void* d_out, int out_size) {
    (void)in_sizes; (void)n_in; (void)out_size;
    const float* x = (const float*)d_in[0];
    const float* Wq = (const float*)d_in[1];
    const float* Wk = (const float*)d_in[2];
    const float* Wv = (const float*)d_in[3];
    float* out = (float*)d_out;

    cudaFuncSetAttribute(qkv_proj_kernel, cudaFuncAttributeMaxDynamicSharedMemorySize,
                         QKV_SMEM);

    wsplit_kernel<<<(192 * 512 + 255) / 256, 256>>>(Wq, Wk, Wv);
    qkv_proj_kernel<<<MROWS / 128, 512, QKV_SMEM>>>(x);
    attn_kernel<<<dim3(SEQ / 64, BATCH), 128>>>(out);
}